// round 1
// baseline (speedup 1.0000x reference)
#include <cuda_runtime.h>

#define B_    64
#define C_    256
#define HW_   1024
#define NPIX  65536
#define NCODE 1024

__device__ float g_a[NPIX];
__device__ float g_c[NCODE];
__device__ int   g_idx[NPIX];

// ---------------------------------------------------------------------------
// c_j = sum_i fl(w[j][i]^2), sequential non-fused adds (mimic "mul then sum")
// ---------------------------------------------------------------------------
__global__ void c_kernel(const float* __restrict__ w) {
    int j = blockIdx.x * blockDim.x + threadIdx.x;
    if (j < NCODE) {
        const float* r = w + (size_t)j * C_;
        float s = 0.f;
        #pragma unroll 8
        for (int i = 0; i < C_; i++) s = __fadd_rn(s, __fmul_rn(r[i], r[i]));
        g_c[j] = s;
    }
}

// ---------------------------------------------------------------------------
// a_p = sum_i fl(x_p[i]^2), sequential non-fused adds.
// x layout (B,C,H,W): element i of pixel p=(b,hw) at x[b*C*HW + i*HW + hw]
// ---------------------------------------------------------------------------
__global__ void a_kernel(const float* __restrict__ x) {
    int p = blockIdx.x * blockDim.x + threadIdx.x;
    int b = p >> 10, hw = p & 1023;
    const float* base = x + (size_t)b * C_ * HW_ + hw;
    float s = 0.f;
    #pragma unroll 8
    for (int i = 0; i < C_; i++) {
        float v = base[(size_t)i * HW_];
        s = __fadd_rn(s, __fmul_rn(v, v));
    }
    g_a[p] = s;
}

// ---------------------------------------------------------------------------
// Fused distance GEMM + argmin.
// Block: 128 pixels x all 1024 codes (8 chunks of 128 codes).
// smem: xs[k=256][pix=128] (loaded once), ws[k=128][code=128 +pad] per chunk.
// Thread (tx=t&15, ty=t>>4): pixels {ty+16p}, codes {tx+16u}  (stride-16 ->
// conflict-free LDS with broadcast between the two ty halves of a warp).
// d2 = fl( fmaf(-2, dot, a) + c )  -- exactly the reference's rounding.
// ---------------------------------------------------------------------------
__global__ void __launch_bounds__(256, 1)
argmin_kernel(const float* __restrict__ x, const float* __restrict__ wt,
              float* __restrict__ out_idx, int write_idx) {
    extern __shared__ float sm[];
    float* xs = sm;                 // [256][128]
    float* ws = sm + 256 * 128;     // [128][129]

    int t    = threadIdx.x;
    int lane = t & 31, warp = t >> 5;
    int tx   = t & 15, ty   = t >> 4;

    int pix_base = blockIdx.x * 128;           // 128 | 1024 -> single image b
    int b  = pix_base >> 10;
    int hw = pix_base & 1023;
    const float* xb = x + (size_t)b * C_ * HW_ + hw;

    // Load x tile: xs[i][pl], float4, fully coalesced.
    #pragma unroll 4
    for (int it = 0; it < 32; it++) {
        int i = warp + 8 * it;
        float4 v = *reinterpret_cast<const float4*>(xb + (size_t)i * HW_ + lane * 4);
        *reinterpret_cast<float4*>(&xs[i * 128 + lane * 4]) = v;
    }

    float a_reg[8], bd[8];
    int   bi[8];
    #pragma unroll
    for (int p = 0; p < 8; p++) {
        a_reg[p] = g_a[pix_base + ty + 16 * p];
        bd[p]    = 3.4e38f;
        bi[p]    = 0;
    }
    __syncthreads();

    for (int cc = 0; cc < 8; cc++) {
        float acc[8][8];
        #pragma unroll
        for (int p = 0; p < 8; p++)
            #pragma unroll
            for (int u = 0; u < 8; u++) acc[p][u] = 0.f;

        for (int kc = 0; kc < 2; kc++) {
            __syncthreads();
            // Load ws[k][c] transposed (global coalesced on k via float4).
            #pragma unroll
            for (int cit = 0; cit < 16; cit++) {
                int c = warp + 8 * cit;
                float4 v = *reinterpret_cast<const float4*>(
                    wt + (size_t)(cc * 128 + c) * C_ + kc * 128 + lane * 4);
                ws[(lane * 4 + 0) * 129 + c] = v.x;
                ws[(lane * 4 + 1) * 129 + c] = v.y;
                ws[(lane * 4 + 2) * 129 + c] = v.z;
                ws[(lane * 4 + 3) * 129 + c] = v.w;
            }
            __syncthreads();

            #pragma unroll 2
            for (int kk = 0; kk < 128; kk++) {
                int k = kc * 128 + kk;
                float xr[8], wr[8];
                #pragma unroll
                for (int p = 0; p < 8; p++) xr[p] = xs[k * 128 + ty + 16 * p];
                #pragma unroll
                for (int u = 0; u < 8; u++) wr[u] = ws[kk * 129 + tx + 16 * u];
                #pragma unroll
                for (int p = 0; p < 8; p++)
                    #pragma unroll
                    for (int u = 0; u < 8; u++)
                        acc[p][u] = fmaf(xr[p], wr[u], acc[p][u]);
            }
        }

        // Chunk epilogue: ascending-j updates keep first-index-on-tie.
        #pragma unroll
        for (int u = 0; u < 8; u++) {
            int j = cc * 128 + tx + 16 * u;
            float cj = g_c[j];
            #pragma unroll
            for (int p = 0; p < 8; p++) {
                float d2 = __fadd_rn(fmaf(-2.f, acc[p][u], a_reg[p]), cj);
                if (d2 < bd[p] || (d2 == bd[p] && j < bi[p])) {
                    bd[p] = d2;
                    bi[p] = j;
                }
            }
        }
    }

    // Cross-tx reduction (16 candidates per pixel), lexicographic (d2, j).
    __syncthreads();
    float* rd = sm;                       // [128][16]
    int*   ri = (int*)(sm + 2048);        // [128][16]
    #pragma unroll
    for (int p = 0; p < 8; p++) {
        rd[(ty + 16 * p) * 16 + tx] = bd[p];
        ri[(ty + 16 * p) * 16 + tx] = bi[p];
    }
    __syncthreads();
    if (t < 128) {
        float best = rd[t * 16];
        int   bj   = ri[t * 16];
        #pragma unroll
        for (int s = 1; s < 16; s++) {
            float d = rd[t * 16 + s];
            int   j = ri[t * 16 + s];
            if (d < best || (d == best && j < bj)) { best = d; bj = j; }
        }
        g_idx[pix_base + t] = bj;
        if (write_idx) out_idx[pix_base + t] = (float)bj;
    }
}

// ---------------------------------------------------------------------------
// Scatter: quantized[b][ci][hw] = w[idx][ci];  ste = fl(fl(q-x)+x).
// smem transpose so both the codebook gather and the output writes coalesce.
// ---------------------------------------------------------------------------
__global__ void __launch_bounds__(256, 1)
scatter_kernel(const float* __restrict__ x, const float* __restrict__ wt,
               float* __restrict__ out_q, float* __restrict__ out_ste,
               int has_ste) {
    extern __shared__ float sm[];          // [256][129]
    __shared__ int lidx[128];

    int t = threadIdx.x, lane = t & 31, warp = t >> 5;
    int pix_base = blockIdx.x * 128;
    int b  = pix_base >> 10;
    int hw = pix_base & 1023;

    if (t < 128) lidx[t] = g_idx[pix_base + t];
    __syncthreads();

    // Gather codebook rows (coalesced reads, conflict-free transposed stores).
    for (int rit = 0; rit < 16; rit++) {
        int r = warp + 8 * rit;
        const float* row = wt + (size_t)lidx[r] * C_;
        #pragma unroll
        for (int kit = 0; kit < 8; kit++) {
            int ci = lane + 32 * kit;
            sm[ci * 129 + r] = row[ci];
        }
    }
    __syncthreads();

    int hw_l = t & 127;
    int ch   = t >> 7;                     // 0..1
    for (int cit = 0; cit < 128; cit++) {
        int ci = ch + 2 * cit;
        size_t o = (size_t)b * C_ * HW_ + (size_t)ci * HW_ + hw + hw_l;
        float q = sm[ci * 129 + hw_l];
        out_q[o] = q;
        if (has_ste) {
            float xv = x[o];
            out_ste[o] = __fadd_rn(__fsub_rn(q, xv), xv);
        }
    }
}

// ---------------------------------------------------------------------------
extern "C" void kernel_launch(void* const* d_in, const int* in_sizes, int n_in,
                              void* d_out, int out_size) {
    const float* x  = (const float*)d_in[0];
    const float* wt = (const float*)d_in[1];
    float* out = (float*)d_out;

    const long long qsz = (long long)NPIX * C_;  // 16777216
    int has_ste = (out_size >= (int)(2 * qsz)) ? 1 : 0;
    int has_idx = (out_size >= (int)(2 * qsz) + NPIX) ||
                  (out_size == (int)qsz + NPIX);
    float* out_q   = out;
    float* out_ste = out + qsz;
    float* out_idx = has_ste ? out + 2 * qsz : out + qsz;

    cudaFuncSetAttribute(argmin_kernel,
        cudaFuncAttributeMaxDynamicSharedMemorySize, 197120);
    cudaFuncSetAttribute(scatter_kernel,
        cudaFuncAttributeMaxDynamicSharedMemorySize, 132096);

    c_kernel<<<4, 256>>>(wt);
    a_kernel<<<NPIX / 256, 256>>>(x);
    argmin_kernel<<<NPIX / 128, 256, 197120>>>(x, wt, out_idx, has_idx ? 1 : 0);
    scatter_kernel<<<NPIX / 128, 256, 132096>>>(x, wt, out_q, out_ste, has_ste);
}